// round 15
// baseline (speedup 1.0000x reference)
#include <cuda_runtime.h>

// SuperLoss: loss = w*(w+2), w = W(y), y = L/2, L = softplus(pr) - pr*gt.
// Identity: sigma = exp(-W(y)) = W(y)/y  =>  sigma*L = 2w, log(sigma)^2 = w^2.
// BETA0 clamp provably dead: gt in [0,1] => L > 0 => y > 0 > BETA0/2.
// W via Pade[2/2] init + 1 Halley step -> loss rel err ~1.3e-7 (measured).
//
// Session conclusion (R3-R14): bench steady state is sustained-HBM-bound at
// ~6.2 TB/s over 384 MB irreducible fp32 traffic => ~62us wallclock floor,
// run-to-run noise +/-0.5us. This kernel has the lowest intrinsic time of all
// variants (ncu 53.5us, DRAM 84.8%): dense grid, predicate-free, 4 front-
// batched LDG.128/thread, evict-first streaming, 32 regs.

__device__ __forceinline__ float ex2f(float x) { float r; asm("ex2.approx.ftz.f32 %0, %1;" : "=f"(r) : "f"(x)); return r; }
__device__ __forceinline__ float lg2f(float x) { float r; asm("lg2.approx.ftz.f32 %0, %1;" : "=f"(r) : "f"(x)); return r; }
__device__ __forceinline__ float rcpf(float x) { float r; asm("rcp.approx.ftz.f32 %0, %1;" : "=f"(r) : "f"(x)); return r; }

__device__ __forceinline__ float superloss_elem(float a, float g) {
    // stable softplus: log(1 + e^a) = max(a,0) + ln2 * lg2(1 + 2^(-|a|*log2e))
    float t  = ex2f(-fabsf(a) * 1.4426950408889634f);
    float lg = lg2f(1.0f + t);
    float m  = fmaxf(a, 0.0f);
    float u  = fmaf(-0.5f * a, g, 0.5f * m);
    float y  = fmaf(lg, 0.34657359027997264f, u);     // y = L/2

    // Pade[2/2] init: w0 = y(1 + 1.9y + 0.28333y^2)/(1 + 2.9y + 1.68333y^2)
    float num = y * fmaf(y, fmaf(0.2833333f, y, 1.9f), 1.0f);
    float den = fmaf(y, fmaf(1.6833333f, y, 2.9f), 1.0f);
    float w   = num * rcpf(den);

    // 1 Halley iteration (single reciprocal)
    float e  = ex2f(w * 1.4426950408889634f);
    float f  = fmaf(w, e, -y);               // w*e^w - y
    float tp = fmaf(2.0f, w, 2.0f);          // 2w + 2
    float dn = fmaf(e * (w + 1.0f), tp, -(w + 2.0f) * f);
    w = fmaf(-f * tp, rcpf(dn), w);

    // loss = 2w + w^2
    return w * (w + 2.0f);
}

__device__ __forceinline__ void compute_store(float4 a, float4 g, float4* dst) {
    float4 r;
    r.x = superloss_elem(a.x, g.x);
    r.y = superloss_elem(a.y, g.y);
    r.z = superloss_elem(a.z, g.z);
    r.w = superloss_elem(a.w, g.w);
    __stcs(dst, r);
}

// Exact-size kernel: nv divisible by 512, no predicates, 4 front-batched LDG.128.
__global__ void __launch_bounds__(256) superloss_kernel_v8_exact(
        const float4* __restrict__ pr,
        const float4* __restrict__ gt,
        float4* __restrict__ out) {
    int i0 = blockIdx.x * (256 * 2) + threadIdx.x;
    int i1 = i0 + 256;

    float4 a0 = __ldcs(pr + i0);
    float4 g0 = __ldcs(gt + i0);
    float4 a1 = __ldcs(pr + i1);
    float4 g1 = __ldcs(gt + i1);

    compute_store(a0, g0, out + i0);
    compute_store(a1, g1, out + i1);
}

// Generic fallback (predicated) for sizes that don't tile exactly.
__global__ void __launch_bounds__(256) superloss_kernel_v8(
        const float4* __restrict__ pr,
        const float4* __restrict__ gt,
        float4* __restrict__ out, int n4) {
    int i0 = blockIdx.x * (256 * 2) + threadIdx.x;
    int i1 = i0 + 256;
    bool p0 = i0 < n4;
    bool p1 = i1 < n4;

    float4 a0, a1, g0, g1;
    if (p0) { a0 = __ldcs(pr + i0); g0 = __ldcs(gt + i0); }
    if (p1) { a1 = __ldcs(pr + i1); g1 = __ldcs(gt + i1); }

    if (p0) compute_store(a0, g0, out + i0);
    if (p1) compute_store(a1, g1, out + i1);
}

__global__ void superloss_kernel_tail(const float* __restrict__ pr,
                                      const float* __restrict__ gt,
                                      float* __restrict__ out, int start, int n) {
    int i = start + blockIdx.x * blockDim.x + threadIdx.x;
    if (i < n) out[i] = superloss_elem(pr[i], gt[i]);
}

extern "C" void kernel_launch(void* const* d_in, const int* in_sizes, int n_in,
                              void* d_out, int out_size) {
    const float* pr = (const float*)d_in[0];
    const float* gt = (const float*)d_in[1];
    float* out = (float*)d_out;
    int n  = out_size;
    int n4 = n >> 2;
    const int per_block = 256 * 2;

    if (n4 > 0 && (n & 3) == 0 && (n4 % per_block) == 0) {
        superloss_kernel_v8_exact<<<n4 / per_block, 256>>>(
            (const float4*)pr, (const float4*)gt, (float4*)out);
        return;
    }

    if (n4 > 0) {
        int blocks = (n4 + per_block - 1) / per_block;
        superloss_kernel_v8<<<blocks, 256>>>(
            (const float4*)pr, (const float4*)gt, (float4*)out, n4);
    }
    int tail_start = n4 << 2;
    int tail = n - tail_start;
    if (tail > 0) {
        superloss_kernel_tail<<<1, 128>>>(pr, gt, out, tail_start, n);
    }
}

// round 16
// speedup vs baseline: 1.1103x; 1.1103x over previous
#include <cuda_runtime.h>

// SuperLoss: loss = w*(w+2), w = W(y), y = L/2, L = softplus(pr) - pr*gt.
// Identity: sigma = exp(-W(y)) = W(y)/y  =>  sigma*L = 2w, log(sigma)^2 = w^2.
// BETA0 clamp provably dead: gt in [0,1] => L > 0 => y > 0 > BETA0/2.
// W via Pade[2/2] init + 1 Halley step -> loss rel err ~1.3e-7 (measured).
//
// Session conclusion (R3-R15): 384 MB irreducible fp32 traffic; healthy-
// container sustained HBM ~6.2-6.7 TB/s => ~62us bench floor. Cross-hold
// variance is +/-3-6us (R6 vs R15: identical binary, ncu 53.5 vs 66.5us —
// container clock state, not code). This source is the lowest-intrinsic-cost
// validated variant: dense grid, predicate-free, 4 front-batched LDG.128,
// evict-first streaming, 32 regs, ~20 FMA + 5 MUFU per element.

__device__ __forceinline__ float ex2f(float x) { float r; asm("ex2.approx.ftz.f32 %0, %1;" : "=f"(r) : "f"(x)); return r; }
__device__ __forceinline__ float lg2f(float x) { float r; asm("lg2.approx.ftz.f32 %0, %1;" : "=f"(r) : "f"(x)); return r; }
__device__ __forceinline__ float rcpf(float x) { float r; asm("rcp.approx.ftz.f32 %0, %1;" : "=f"(r) : "f"(x)); return r; }

__device__ __forceinline__ float superloss_elem(float a, float g) {
    // stable softplus: log(1 + e^a) = max(a,0) + ln2 * lg2(1 + 2^(-|a|*log2e))
    float t  = ex2f(-fabsf(a) * 1.4426950408889634f);
    float lg = lg2f(1.0f + t);
    float m  = fmaxf(a, 0.0f);
    float u  = fmaf(-0.5f * a, g, 0.5f * m);
    float y  = fmaf(lg, 0.34657359027997264f, u);     // y = L/2

    // Pade[2/2] init: w0 = y(1 + 1.9y + 0.28333y^2)/(1 + 2.9y + 1.68333y^2)
    float num = y * fmaf(y, fmaf(0.2833333f, y, 1.9f), 1.0f);
    float den = fmaf(y, fmaf(1.6833333f, y, 2.9f), 1.0f);
    float w   = num * rcpf(den);

    // 1 Halley iteration (single reciprocal)
    float e  = ex2f(w * 1.4426950408889634f);
    float f  = fmaf(w, e, -y);               // w*e^w - y
    float tp = fmaf(2.0f, w, 2.0f);          // 2w + 2
    float dn = fmaf(e * (w + 1.0f), tp, -(w + 2.0f) * f);
    w = fmaf(-f * tp, rcpf(dn), w);

    // loss = 2w + w^2
    return w * (w + 2.0f);
}

__device__ __forceinline__ void compute_store(float4 a, float4 g, float4* dst) {
    float4 r;
    r.x = superloss_elem(a.x, g.x);
    r.y = superloss_elem(a.y, g.y);
    r.z = superloss_elem(a.z, g.z);
    r.w = superloss_elem(a.w, g.w);
    __stcs(dst, r);
}

// Exact-size kernel: nv divisible by 512, no predicates, 4 front-batched LDG.128.
__global__ void __launch_bounds__(256) superloss_kernel_v8_exact(
        const float4* __restrict__ pr,
        const float4* __restrict__ gt,
        float4* __restrict__ out) {
    int i0 = blockIdx.x * (256 * 2) + threadIdx.x;
    int i1 = i0 + 256;

    float4 a0 = __ldcs(pr + i0);
    float4 g0 = __ldcs(gt + i0);
    float4 a1 = __ldcs(pr + i1);
    float4 g1 = __ldcs(gt + i1);

    compute_store(a0, g0, out + i0);
    compute_store(a1, g1, out + i1);
}

// Generic fallback (predicated) for sizes that don't tile exactly.
__global__ void __launch_bounds__(256) superloss_kernel_v8(
        const float4* __restrict__ pr,
        const float4* __restrict__ gt,
        float4* __restrict__ out, int n4) {
    int i0 = blockIdx.x * (256 * 2) + threadIdx.x;
    int i1 = i0 + 256;
    bool p0 = i0 < n4;
    bool p1 = i1 < n4;

    float4 a0, a1, g0, g1;
    if (p0) { a0 = __ldcs(pr + i0); g0 = __ldcs(gt + i0); }
    if (p1) { a1 = __ldcs(pr + i1); g1 = __ldcs(gt + i1); }

    if (p0) compute_store(a0, g0, out + i0);
    if (p1) compute_store(a1, g1, out + i1);
}

__global__ void superloss_kernel_tail(const float* __restrict__ pr,
                                      const float* __restrict__ gt,
                                      float* __restrict__ out, int start, int n) {
    int i = start + blockIdx.x * blockDim.x + threadIdx.x;
    if (i < n) out[i] = superloss_elem(pr[i], gt[i]);
}

extern "C" void kernel_launch(void* const* d_in, const int* in_sizes, int n_in,
                              void* d_out, int out_size) {
    const float* pr = (const float*)d_in[0];
    const float* gt = (const float*)d_in[1];
    float* out = (float*)d_out;
    int n  = out_size;
    int n4 = n >> 2;
    const int per_block = 256 * 2;

    if (n4 > 0 && (n & 3) == 0 && (n4 % per_block) == 0) {
        superloss_kernel_v8_exact<<<n4 / per_block, 256>>>(
            (const float4*)pr, (const float4*)gt, (float4*)out);
        return;
    }

    if (n4 > 0) {
        int blocks = (n4 + per_block - 1) / per_block;
        superloss_kernel_v8<<<blocks, 256>>>(
            (const float4*)pr, (const float4*)gt, (float4*)out, n4);
    }
    int tail_start = n4 << 2;
    int tail = n - tail_start;
    if (tail > 0) {
        superloss_kernel_tail<<<1, 128>>>(pr, gt, out, tail_start, n);
    }
}